// round 5
// baseline (speedup 1.0000x reference)
#include <cuda_runtime.h>
#include <cuda_bf16.h>
#include <cuda_fp16.h>
#include <cstdint>

// ============================================================================
// Problem dims
// ============================================================================
static constexpr int Mtot = 8192;
static constexpr int Hdim = 4096;
static constexpr int Idim = 11008;

static constexpr int BM = 128;
static constexpr int MT = Mtot / BM;          // 64

// gate/up (int8): BN=32 per output, BK=64 int8 (64B rows)
static constexpr int NT_GU  = Idim / 32;      // 344
static constexpr int NCH_GU = Hdim / 64;      // 64
static constexpr int STG_GU = 20480;          // Ah 8K, Al 8K, Bg 2K, Bu 2K
static constexpr int NST_GU = 5;
static constexpr int SMEM_GU = NST_GU * STG_GU;   // 102400

// down (fp16): BN=128, BK=32 halves (64B rows)
static constexpr int NT_DN  = Hdim / 128;     // 32
static constexpr int NCH_DN = Idim / 32;      // 344
static constexpr int STG_DN = 16384;          // A 8K, B 8K
static constexpr int NST_DN = 6;
static constexpr int SMEM_DN = NST_DN * STG_DN;   // 98304

// ============================================================================
// Device scratch
// ============================================================================
__device__ signed char g_gate8[(size_t)Idim * Hdim];
__device__ signed char g_up8  [(size_t)Idim * Hdim];
__device__ __half      g_dw16 [(size_t)Hdim * Idim];
__device__ signed char g_xh   [(size_t)Mtot * Hdim];
__device__ signed char g_xl   [(size_t)Mtot * Hdim];
__device__ float       g_xs   [Mtot];
__device__ __half      g_p16  [(size_t)Mtot * Idim];

// ============================================================================
// Primitives (sm_80-era PTX only; compute_103-safe)
// ============================================================================
__device__ __forceinline__ uint32_t smem_u32(const void* p) {
    uint32_t a;
    asm("{ .reg .u64 t; cvta.to.shared.u64 t, %1; cvt.u32.u64 %0, t; }" : "=r"(a) : "l"(p));
    return a;
}
__device__ __forceinline__ void cpa16(uint32_t s, const void* g) {
    asm volatile("cp.async.cg.shared.global [%0], [%1], 16;" :: "r"(s), "l"(g));
}
#define CP_COMMIT() asm volatile("cp.async.commit_group;" ::: "memory")
#define CP_WAIT(N)  asm volatile("cp.async.wait_group %0;" :: "n"(N) : "memory")

#define LDSM4(r, addr) \
    asm volatile("ldmatrix.sync.aligned.m8n8.x4.shared.b16 {%0,%1,%2,%3}, [%4];" \
        : "=r"((r)[0]), "=r"((r)[1]), "=r"((r)[2]), "=r"((r)[3]) : "r"(addr))

// int8: D(s32) += A(s8 16x32) * B(s8 8x32)
#define MMAS8(d, a, b0, b1) \
    asm volatile("mma.sync.aligned.m16n8k32.row.col.s32.s8.s8.s32 " \
        "{%0,%1,%2,%3}, {%4,%5,%6,%7}, {%8,%9}, {%0,%1,%2,%3};" \
        : "+r"((d)[0]), "+r"((d)[1]), "+r"((d)[2]), "+r"((d)[3]) \
        : "r"((a)[0]), "r"((a)[1]), "r"((a)[2]), "r"((a)[3]), "r"(b0), "r"(b1))

// fp16: D(f32) += A(f16 16x16) * B(f16 8x16)
#define MMAF16(d, a, b0, b1) \
    asm volatile("mma.sync.aligned.m16n8k16.row.col.f32.f16.f16.f32 " \
        "{%0,%1,%2,%3}, {%4,%5,%6,%7}, {%8,%9}, {%0,%1,%2,%3};" \
        : "+f"((d)[0]), "+f"((d)[1]), "+f"((d)[2]), "+f"((d)[3]) \
        : "r"((a)[0]), "r"((a)[1]), "r"((a)[2]), "r"((a)[3]), "r"(b0), "r"(b1))

// 64B rows, 4x16B chunks, chunk swizzle c ^ ((r>>1)&3) (verified conflict-free in R4)
__device__ __forceinline__ uint32_t swz(uint32_t base, int r, int c) {
    return base + r * 64 + ((c ^ ((r >> 1) & 3)) << 4);
}
__device__ __forceinline__ uint32_t swzoff(int r, int lc) {
    return (uint32_t)(r * 64 + ((lc ^ ((r >> 1) & 3)) << 4));
}

__device__ __forceinline__ void tile_coords(int bid, int nt, int& mt, int& ntile) {
    const int GROUP_M = 8;
    int per_group = GROUP_M * nt;
    int g = bid / per_group;
    int r = bid % per_group;
    int base = g * GROUP_M;
    int gm = MT - base; if (gm > GROUP_M) gm = GROUP_M;
    mt = base + (r % gm);
    ntile = r / gm;
}

// ============================================================================
// Prep 1: pack weights. gate/up -> int8 (exact), down -> fp16 (exact, |w|<=127)
// ============================================================================
__global__ void pack_weights(const int* __restrict__ gq, const int* __restrict__ uq,
                             const int* __restrict__ dq) {
    size_t i = (size_t)blockIdx.x * blockDim.x + threadIdx.x;
    size_t n4 = (size_t)Idim * Hdim / 4;
    if (i >= n4) return;
    int4 a = reinterpret_cast<const int4*>(gq)[i];
    reinterpret_cast<char4*>(g_gate8)[i] =
        make_char4((signed char)a.x, (signed char)a.y, (signed char)a.z, (signed char)a.w);
    int4 b = reinterpret_cast<const int4*>(uq)[i];
    reinterpret_cast<char4*>(g_up8)[i] =
        make_char4((signed char)b.x, (signed char)b.y, (signed char)b.z, (signed char)b.w);
    int4 c = reinterpret_cast<const int4*>(dq)[i];
    __half2 d0 = __floats2half2_rn((float)c.x, (float)c.y);
    __half2 d1 = __floats2half2_rn((float)c.z, (float)c.w);
    uint2 dd; dd.x = *reinterpret_cast<uint32_t*>(&d0); dd.y = *reinterpret_cast<uint32_t*>(&d1);
    reinterpret_cast<uint2*>(g_dw16)[i] = dd;
}

// ============================================================================
// Prep 2: per-token 15-bit quantization of x:  x ~= s*(128*h + l), h,l in int8
// One block per row; 256 threads x 16 elems.
// ============================================================================
__global__ __launch_bounds__(256)
void quant_x(const float* __restrict__ x) {
    __shared__ float warpmax[8];
    const int row = blockIdx.x, tid = threadIdx.x;
    const float* xr = x + (size_t)row * Hdim;
    float4 v[4];
    float mx = 0.f;
    #pragma unroll
    for (int i = 0; i < 4; ++i) {
        v[i] = reinterpret_cast<const float4*>(xr)[tid + i * 256];
        mx = fmaxf(mx, fmaxf(fmaxf(fabsf(v[i].x), fabsf(v[i].y)),
                             fmaxf(fabsf(v[i].z), fabsf(v[i].w))));
    }
    #pragma unroll
    for (int o = 16; o > 0; o >>= 1) mx = fmaxf(mx, __shfl_xor_sync(0xffffffffu, mx, o));
    if ((tid & 31) == 0) warpmax[tid >> 5] = mx;
    __syncthreads();
    if (tid < 32) {
        float m = (tid < 8) ? warpmax[tid] : 0.f;
        #pragma unroll
        for (int o = 4; o > 0; o >>= 1) m = fmaxf(m, __shfl_xor_sync(0xffffffffu, m, o));
        if (tid == 0) warpmax[0] = m;
    }
    __syncthreads();
    mx = warpmax[0];
    const float inv = (mx > 0.f) ? (16256.0f / mx) : 0.f;
    if (tid == 0) g_xs[row] = (mx > 0.f) ? (mx / 16256.0f) : 0.f;

    #pragma unroll
    for (int i = 0; i < 4; ++i) {
        float f[4] = {v[i].x, v[i].y, v[i].z, v[i].w};
        signed char hc[4], lc4[4];
        #pragma unroll
        for (int j = 0; j < 4; ++j) {
            float vv = f[j] * inv;
            float h = rintf(vv * 0.0078125f);          // /128
            float l = rintf(vv - 128.0f * h);
            hc[j] = (signed char)(int)h;
            lc4[j] = (signed char)(int)l;
        }
        size_t o4 = (size_t)row * (Hdim / 4) + tid + i * 256;
        reinterpret_cast<char4*>(g_xh)[o4] = make_char4(hc[0], hc[1], hc[2], hc[3]);
        reinterpret_cast<char4*>(g_xl)[o4] = make_char4(lc4[0], lc4[1], lc4[2], lc4[3]);
    }
}

// ============================================================================
// Kernel A: fused gate+up int8 GEMM -> p (fp16)
// CTA: 128(M) x 32(N per output). 8 warps 4m x 2n; warp tile 32x16 per output.
// 2 int8 passes (h,l) into separate s32 accumulators.
// ============================================================================
__global__ __launch_bounds__(256, 2)
void gemm_gateup(const float* __restrict__ gate_scale, const float* __restrict__ up_scale) {
    extern __shared__ __align__(128) char smem[];
    const uint32_t s0 = smem_u32(smem);
    const int tid = threadIdx.x;
    const int wid = tid >> 5, lane = tid & 31;
    const int rsel = lane & 15, csel = lane >> 4;
    const int wm = (wid & 3) * 32, wn = (wid >> 2) * 16;

    int mt, nt; tile_coords(blockIdx.x, NT_GU, mt, nt);
    const int m0 = mt * BM, n0 = nt * 32;

    const signed char* pAh = g_xh + (size_t)m0 * Hdim;
    const signed char* pAl = g_xl + (size_t)m0 * Hdim;

    // loader: lr = row (0..63), lc = 16B chunk (0..3)
    const int lr = tid >> 2, lc = tid & 3;
    const uint32_t offA1 = swzoff(lr, lc);
    const uint32_t offA2 = swzoff(lr + 64, lc);
    const uint32_t offB  = 16384 + swzoff(lr, lc);   // rows 32..63 land in Bu region
    const signed char* pBrow = (lr < 32)
        ? g_gate8 + (size_t)(n0 + lr) * Hdim
        : g_up8   + (size_t)(n0 + lr - 32) * Hdim;

    auto load_chunk = [&](int ch, int st) {
        uint32_t sb = s0 + st * STG_GU;
        size_t ga1 = (size_t)lr * Hdim + ch * 64 + lc * 16;
        size_t ga2 = (size_t)(lr + 64) * Hdim + ch * 64 + lc * 16;
        cpa16(sb + offA1,        pAh + ga1);
        cpa16(sb + offA2,        pAh + ga2);
        cpa16(sb + 8192 + offA1, pAl + ga1);
        cpa16(sb + 8192 + offA2, pAl + ga2);
        cpa16(sb + offB,         pBrow + ch * 64 + lc * 16);
        CP_COMMIT();
    };

    int cgh[2][2][4], cgl[2][2][4], cuh[2][2][4], cul[2][2][4];
    #pragma unroll
    for (int g = 0; g < 2; ++g)
        #pragma unroll
        for (int n = 0; n < 2; ++n)
            #pragma unroll
            for (int j = 0; j < 4; ++j) {
                cgh[g][n][j] = 0; cgl[g][n][j] = 0; cuh[g][n][j] = 0; cul[g][n][j] = 0;
            }

    #pragma unroll
    for (int p = 0; p < NST_GU - 1; ++p) load_chunk(p, p);

    for (int ch = 0; ch < NCH_GU; ++ch) {
        CP_WAIT(NST_GU - 2);
        __syncthreads();
        int nx = ch + NST_GU - 1;
        if (nx < NCH_GU) load_chunk(nx, nx % NST_GU);
        const uint32_t sb = s0 + (ch % NST_GU) * STG_GU;
        #pragma unroll
        for (int s = 0; s < 2; ++s) {
            uint32_t ah[2][4], al[2][4], bg[4], bu[4];
            #pragma unroll
            for (int g = 0; g < 2; ++g) {
                LDSM4(ah[g], swz(sb,        wm + g * 16 + rsel, 2 * s + csel));
                LDSM4(al[g], swz(sb + 8192, wm + g * 16 + rsel, 2 * s + csel));
            }
            LDSM4(bg, swz(sb + 16384, wn + rsel, 2 * s + csel));
            LDSM4(bu, swz(sb + 18432, wn + rsel, 2 * s + csel));
            #pragma unroll
            for (int g = 0; g < 2; ++g) {
                MMAS8(cgh[g][0], ah[g], bg[0], bg[2]);
                MMAS8(cgh[g][1], ah[g], bg[1], bg[3]);
                MMAS8(cuh[g][0], ah[g], bu[0], bu[2]);
                MMAS8(cuh[g][1], ah[g], bu[1], bu[3]);
                MMAS8(cgl[g][0], al[g], bg[0], bg[2]);
                MMAS8(cgl[g][1], al[g], bg[1], bg[3]);
                MMAS8(cul[g][0], al[g], bu[0], bu[2]);
                MMAS8(cul[g][1], al[g], bu[1], bu[3]);
            }
        }
    }

    // Epilogue: g = xs*(128*Ah+Al)*gs ; u likewise ; p = g*u -> half2
    #pragma unroll
    for (int n = 0; n < 2; ++n) {
        const int cn = n0 + wn + n * 8 + (lane & 3) * 2;
        const float gs0 = gate_scale[cn], gs1 = gate_scale[cn + 1];
        const float us0 = up_scale[cn],   us1 = up_scale[cn + 1];
        #pragma unroll
        for (int g = 0; g < 2; ++g) {
            const int rr = m0 + wm + g * 16 + (lane >> 2);
            const float xs0 = g_xs[rr], xs1 = g_xs[rr + 8];
            float gv0 = xs0 * fmaf(128.f, (float)cgh[g][n][0], (float)cgl[g][n][0]) * gs0;
            float gv1 = xs0 * fmaf(128.f, (float)cgh[g][n][1], (float)cgl[g][n][1]) * gs1;
            float gv2 = xs1 * fmaf(128.f, (float)cgh[g][n][2], (float)cgl[g][n][2]) * gs0;
            float gv3 = xs1 * fmaf(128.f, (float)cgh[g][n][3], (float)cgl[g][n][3]) * gs1;
            float uv0 = xs0 * fmaf(128.f, (float)cuh[g][n][0], (float)cul[g][n][0]) * us0;
            float uv1 = xs0 * fmaf(128.f, (float)cuh[g][n][1], (float)cul[g][n][1]) * us1;
            float uv2 = xs1 * fmaf(128.f, (float)cuh[g][n][2], (float)cul[g][n][2]) * us0;
            float uv3 = xs1 * fmaf(128.f, (float)cuh[g][n][3], (float)cul[g][n][3]) * us1;
            __half2 p0 = __floats2half2_rn(gv0 * uv0, gv1 * uv1);
            __half2 p1 = __floats2half2_rn(gv2 * uv2, gv3 * uv3);
            *reinterpret_cast<__half2*>(&g_p16[(size_t)rr * Idim + cn]) = p0;
            *reinterpret_cast<__half2*>(&g_p16[(size_t)(rr + 8) * Idim + cn]) = p1;
        }
    }
}

// ============================================================================
// Kernel B: down GEMM (fp16 single pass).  out = down_scale * (p @ dw^T)
// CTA: 128(M) x 128(N). 8 warps 4m x 2n; warp tile 32x64.
// ============================================================================
__global__ __launch_bounds__(256, 2)
void gemm_down(const float* __restrict__ down_scale, float* __restrict__ out) {
    extern __shared__ __align__(128) char smem[];
    const uint32_t s0 = smem_u32(smem);
    const int tid = threadIdx.x;
    const int wid = tid >> 5, lane = tid & 31;
    const int rsel = lane & 15, csel = lane >> 4;
    const int wm = (wid & 3) * 32, wn = (wid >> 2) * 64;

    int mt, nt; tile_coords(blockIdx.x, NT_DN, mt, nt);
    const int m0 = mt * BM, n0 = nt * 128;

    const __half* pA = g_p16  + (size_t)m0 * Idim;
    const __half* pB = g_dw16 + (size_t)n0 * Idim;

    const int lr = tid >> 2, lc = tid & 3;
    const uint32_t offA1 = swzoff(lr, lc);
    const uint32_t offA2 = swzoff(lr + 64, lc);

    auto load_chunk = [&](int ch, int st) {
        uint32_t sb = s0 + st * STG_DN;
        size_t ga1 = (size_t)lr * Idim + ch * 32 + lc * 8;         // halves
        size_t ga2 = (size_t)(lr + 64) * Idim + ch * 32 + lc * 8;
        cpa16(sb + offA1,        pA + ga1);
        cpa16(sb + offA2,        pA + ga2);
        cpa16(sb + 8192 + offA1, pB + ga1);
        cpa16(sb + 8192 + offA2, pB + ga2);
        CP_COMMIT();
    };

    float cd[2][8][4];
    #pragma unroll
    for (int g = 0; g < 2; ++g)
        #pragma unroll
        for (int n = 0; n < 8; ++n)
            #pragma unroll
            for (int j = 0; j < 4; ++j) cd[g][n][j] = 0.f;

    #pragma unroll
    for (int p = 0; p < NST_DN - 1; ++p) load_chunk(p, p);

    for (int ch = 0; ch < NCH_DN; ++ch) {
        CP_WAIT(NST_DN - 2);
        __syncthreads();
        int nx = ch + NST_DN - 1;
        if (nx < NCH_DN) load_chunk(nx, nx % NST_DN);
        const uint32_t sb = s0 + (ch % NST_DN) * STG_DN;
        #pragma unroll
        for (int s = 0; s < 2; ++s) {
            uint32_t ah[2][4], bb[4][4];
            #pragma unroll
            for (int g = 0; g < 2; ++g)
                LDSM4(ah[g], swz(sb, wm + g * 16 + rsel, 2 * s + csel));
            #pragma unroll
            for (int bt = 0; bt < 4; ++bt)
                LDSM4(bb[bt], swz(sb + 8192, wn + bt * 16 + rsel, 2 * s + csel));
            #pragma unroll
            for (int g = 0; g < 2; ++g)
                #pragma unroll
                for (int n = 0; n < 8; ++n) {
                    int bt = n >> 1, sub = n & 1;
                    MMAF16(cd[g][n], ah[g], bb[bt][sub], bb[bt][2 + sub]);
                }
        }
    }

    #pragma unroll
    for (int n = 0; n < 8; ++n) {
        const int cn = n0 + wn + n * 8 + (lane & 3) * 2;
        const float ds0 = down_scale[cn], ds1 = down_scale[cn + 1];
        #pragma unroll
        for (int g = 0; g < 2; ++g) {
            const int rr = m0 + wm + g * 16 + (lane >> 2);
            float2 v0 = make_float2(cd[g][n][0] * ds0, cd[g][n][1] * ds1);
            float2 v1 = make_float2(cd[g][n][2] * ds0, cd[g][n][3] * ds1);
            *reinterpret_cast<float2*>(&out[(size_t)rr * Hdim + cn]) = v0;
            *reinterpret_cast<float2*>(&out[(size_t)(rr + 8) * Hdim + cn]) = v1;
        }
    }
}

// ============================================================================
// Launch
// ============================================================================
extern "C" void kernel_launch(void* const* d_in, const int* in_sizes, int n_in,
                              void* d_out, int out_size) {
    (void)in_sizes; (void)n_in; (void)out_size;
    const float* x          = (const float*)d_in[0];
    const int*   gate_wq    = (const int*)  d_in[1];
    const float* gate_scale = (const float*)d_in[2];
    const int*   up_wq      = (const int*)  d_in[3];
    const float* up_scale   = (const float*)d_in[4];
    const int*   down_wq    = (const int*)  d_in[5];
    const float* down_scale = (const float*)d_in[6];
    float* out = (float*)d_out;

    cudaFuncSetAttribute(gemm_gateup, cudaFuncAttributeMaxDynamicSharedMemorySize, SMEM_GU);
    cudaFuncSetAttribute(gemm_down,   cudaFuncAttributeMaxDynamicSharedMemorySize, SMEM_DN);

    size_t n4 = (size_t)Idim * Hdim / 4;
    pack_weights<<<(unsigned)((n4 + 255) / 256), 256>>>(gate_wq, up_wq, down_wq);
    quant_x<<<Mtot, 256>>>(x);

    gemm_gateup<<<MT * NT_GU, 256, SMEM_GU>>>(gate_scale, up_scale);
    gemm_down<<<MT * NT_DN, 256, SMEM_DN>>>(down_scale, out);
}

// round 6
// speedup vs baseline: 3.4751x; 3.4751x over previous
#include <cuda_runtime.h>
#include <cuda_fp16.h>
#include <cstdint>

// ============================================================================
// Problem dims
// ============================================================================
static constexpr int Mtot = 8192;
static constexpr int Hdim = 4096;
static constexpr int Idim = 11008;

static constexpr int BM = 128;
static constexpr int MT = Mtot / BM;          // 64

// gate/up (fp16): BN=64 per output, BK=32 halves (64B rows)
static constexpr int NT_GU  = Idim / 64;      // 172
static constexpr int NCH_GU = Hdim / 32;      // 128
static constexpr int STG_GU = 16384;          // A 8K, Bg 4K, Bu 4K
static constexpr int NST_GU = 6;
static constexpr int SMEM_GU = NST_GU * STG_GU;   // 98304

// down (fp16): BN=128, BK=32 halves
static constexpr int NT_DN  = Hdim / 128;     // 32
static constexpr int NCH_DN = Idim / 32;      // 344
static constexpr int STG_DN = 16384;          // A 8K, B 8K
static constexpr int NST_DN = 6;
static constexpr int SMEM_DN = NST_DN * STG_DN;   // 98304

// ============================================================================
// Device scratch
// ============================================================================
__device__ __half g_gw16[(size_t)Idim * Hdim];
__device__ __half g_uw16[(size_t)Idim * Hdim];
__device__ __half g_dw16[(size_t)Hdim * Idim];
__device__ __half g_x16 [(size_t)Mtot * Hdim];
__device__ __half g_p16 [(size_t)Mtot * Idim];

// ============================================================================
// Primitives (sm_80-era PTX; compute_103-safe)
// ============================================================================
__device__ __forceinline__ uint32_t smem_u32(const void* p) {
    uint32_t a;
    asm("{ .reg .u64 t; cvta.to.shared.u64 t, %1; cvt.u32.u64 %0, t; }" : "=r"(a) : "l"(p));
    return a;
}
__device__ __forceinline__ void cpa16(uint32_t s, const void* g) {
    asm volatile("cp.async.cg.shared.global [%0], [%1], 16;" :: "r"(s), "l"(g));
}
#define CP_COMMIT() asm volatile("cp.async.commit_group;" ::: "memory")
#define CP_WAIT(N)  asm volatile("cp.async.wait_group %0;" :: "n"(N) : "memory")

#define LDSM4(r, addr) \
    asm volatile("ldmatrix.sync.aligned.m8n8.x4.shared.b16 {%0,%1,%2,%3}, [%4];" \
        : "=r"((r)[0]), "=r"((r)[1]), "=r"((r)[2]), "=r"((r)[3]) : "r"(addr))

#define MMAF16(d, a, b0, b1) \
    asm volatile("mma.sync.aligned.m16n8k16.row.col.f32.f16.f16.f32 " \
        "{%0,%1,%2,%3}, {%4,%5,%6,%7}, {%8,%9}, {%0,%1,%2,%3};" \
        : "+f"((d)[0]), "+f"((d)[1]), "+f"((d)[2]), "+f"((d)[3]) \
        : "r"((a)[0]), "r"((a)[1]), "r"((a)[2]), "r"((a)[3]), "r"(b0), "r"(b1))

// 64B rows, 4x16B chunks, swizzle c ^ ((r>>1)&3) (conflict-free; validated R4/R5)
__device__ __forceinline__ uint32_t swz(uint32_t base, int r, int c) {
    return base + r * 64 + ((c ^ ((r >> 1) & 3)) << 4);
}
__device__ __forceinline__ uint32_t swzoff(int r, int lc) {
    return (uint32_t)(r * 64 + ((lc ^ ((r >> 1) & 3)) << 4));
}

__device__ __forceinline__ void tile_coords(int bid, int nt, int& mt, int& ntile) {
    const int GROUP_M = 8;
    int per_group = GROUP_M * nt;
    int g = bid / per_group;
    int r = bid % per_group;
    int base = g * GROUP_M;
    int gm = MT - base; if (gm > GROUP_M) gm = GROUP_M;
    mt = base + (r % gm);
    ntile = r / gm;
}

// ============================================================================
// Prep: weights -> fp16 (exact, |w|<=127); x -> fp16 (RN)
// ============================================================================
__global__ void pack_weights(const int* __restrict__ gq, const int* __restrict__ uq,
                             const int* __restrict__ dq) {
    size_t i = (size_t)blockIdx.x * blockDim.x + threadIdx.x;
    size_t n4 = (size_t)Idim * Hdim / 4;
    if (i >= n4) return;
    int4 a = reinterpret_cast<const int4*>(gq)[i];
    int4 b = reinterpret_cast<const int4*>(uq)[i];
    int4 c = reinterpret_cast<const int4*>(dq)[i];
    __half2 a0 = __floats2half2_rn((float)a.x, (float)a.y);
    __half2 a1 = __floats2half2_rn((float)a.z, (float)a.w);
    __half2 b0 = __floats2half2_rn((float)b.x, (float)b.y);
    __half2 b1 = __floats2half2_rn((float)b.z, (float)b.w);
    __half2 c0 = __floats2half2_rn((float)c.x, (float)c.y);
    __half2 c1 = __floats2half2_rn((float)c.z, (float)c.w);
    reinterpret_cast<uint2*>(g_gw16)[i] =
        make_uint2(*reinterpret_cast<uint32_t*>(&a0), *reinterpret_cast<uint32_t*>(&a1));
    reinterpret_cast<uint2*>(g_uw16)[i] =
        make_uint2(*reinterpret_cast<uint32_t*>(&b0), *reinterpret_cast<uint32_t*>(&b1));
    reinterpret_cast<uint2*>(g_dw16)[i] =
        make_uint2(*reinterpret_cast<uint32_t*>(&c0), *reinterpret_cast<uint32_t*>(&c1));
}

__global__ void cvt_x(const float* __restrict__ x) {
    size_t i = (size_t)blockIdx.x * blockDim.x + threadIdx.x;
    size_t n4 = (size_t)Mtot * Hdim / 4;
    if (i >= n4) return;
    float4 v = reinterpret_cast<const float4*>(x)[i];
    __half2 h0 = __floats2half2_rn(v.x, v.y);
    __half2 h1 = __floats2half2_rn(v.z, v.w);
    reinterpret_cast<uint2*>(g_x16)[i] =
        make_uint2(*reinterpret_cast<uint32_t*>(&h0), *reinterpret_cast<uint32_t*>(&h1));
}

// ============================================================================
// Kernel A: fused gate+up fp16 GEMM -> p = (g*gs)*(u*us) in fp16
// CTA: 128(M) x 64(N per output). 8 warps 4m x 2n; warp 32x32 per output.
// ============================================================================
__global__ __launch_bounds__(256, 2)
void gemm_gateup(const float* __restrict__ gate_scale, const float* __restrict__ up_scale) {
    extern __shared__ __align__(128) char smem[];
    const uint32_t s0 = smem_u32(smem);
    const int tid = threadIdx.x;
    const int wid = tid >> 5, lane = tid & 31;
    const int rsel = lane & 15, csel = lane >> 4;
    const int wm = (wid & 3) * 32, wn = (wid >> 2) * 32;

    int mt, nt; tile_coords(blockIdx.x, NT_GU, mt, nt);
    const int m0 = mt * BM, n0 = nt * 64;

    const __half* pA  = g_x16  + (size_t)m0 * Hdim;
    const __half* pBg = g_gw16 + (size_t)n0 * Hdim;
    const __half* pBu = g_uw16 + (size_t)n0 * Hdim;

    // loader: lr = row (0..63), lc = 16B chunk (0..3)
    const int lr = tid >> 2, lc = tid & 3;
    const uint32_t offR = swzoff(lr, lc);
    const uint32_t offR2 = swzoff(lr + 64, lc);

    auto load_chunk = [&](int ch, int st) {
        uint32_t sb = s0 + st * STG_GU;
        size_t ga1 = (size_t)lr * Hdim + ch * 32 + lc * 8;         // halves
        size_t ga2 = (size_t)(lr + 64) * Hdim + ch * 32 + lc * 8;
        cpa16(sb + offR,          pA + ga1);                       // A rows 0..63
        cpa16(sb + offR2,         pA + ga2);                       // A rows 64..127
        cpa16(sb + 8192 + offR,   pBg + ga1);                      // Bg rows 0..63
        cpa16(sb + 12288 + offR,  pBu + ga1);                      // Bu rows 0..63
        CP_COMMIT();
    };

    float cg[2][4][4], cu[2][4][4];
    #pragma unroll
    for (int g = 0; g < 2; ++g)
        #pragma unroll
        for (int n = 0; n < 4; ++n)
            #pragma unroll
            for (int j = 0; j < 4; ++j) { cg[g][n][j] = 0.f; cu[g][n][j] = 0.f; }

    #pragma unroll
    for (int p = 0; p < NST_GU - 1; ++p) load_chunk(p, p);

    for (int ch = 0; ch < NCH_GU; ++ch) {
        CP_WAIT(NST_GU - 2);
        __syncthreads();
        int nx = ch + NST_GU - 1;
        if (nx < NCH_GU) load_chunk(nx, nx % NST_GU);
        const uint32_t sb = s0 + (ch % NST_GU) * STG_GU;
        #pragma unroll
        for (int s = 0; s < 2; ++s) {
            uint32_t ah[2][4], bg[2][4], bu[2][4];
            #pragma unroll
            for (int g = 0; g < 2; ++g)
                LDSM4(ah[g], swz(sb, wm + g * 16 + rsel, 2 * s + csel));
            #pragma unroll
            for (int bt = 0; bt < 2; ++bt) {
                LDSM4(bg[bt], swz(sb + 8192,  wn + bt * 16 + rsel, 2 * s + csel));
                LDSM4(bu[bt], swz(sb + 12288, wn + bt * 16 + rsel, 2 * s + csel));
            }
            #pragma unroll
            for (int g = 0; g < 2; ++g)
                #pragma unroll
                for (int n = 0; n < 4; ++n) {
                    int bt = n >> 1, sub = n & 1;
                    MMAF16(cg[g][n], ah[g], bg[bt][sub], bg[bt][2 + sub]);
                    MMAF16(cu[g][n], ah[g], bu[bt][sub], bu[bt][2 + sub]);
                }
        }
    }

    // Epilogue: p = (g*gs)*(u*us) -> half2
    #pragma unroll
    for (int n = 0; n < 4; ++n) {
        const int cn = n0 + wn + n * 8 + (lane & 3) * 2;
        const float gs0 = gate_scale[cn], gs1 = gate_scale[cn + 1];
        const float us0 = up_scale[cn],   us1 = up_scale[cn + 1];
        #pragma unroll
        for (int g = 0; g < 2; ++g) {
            const int rr = m0 + wm + g * 16 + (lane >> 2);
            float p00 = (cg[g][n][0] * gs0) * (cu[g][n][0] * us0);
            float p01 = (cg[g][n][1] * gs1) * (cu[g][n][1] * us1);
            float p10 = (cg[g][n][2] * gs0) * (cu[g][n][2] * us0);
            float p11 = (cg[g][n][3] * gs1) * (cu[g][n][3] * us1);
            __half2 q0 = __floats2half2_rn(p00, p01);
            __half2 q1 = __floats2half2_rn(p10, p11);
            *reinterpret_cast<__half2*>(&g_p16[(size_t)rr * Idim + cn]) = q0;
            *reinterpret_cast<__half2*>(&g_p16[(size_t)(rr + 8) * Idim + cn]) = q1;
        }
    }
}

// ============================================================================
// Kernel B: down GEMM (fp16 single pass).  out = down_scale * (p @ dw^T)
// CTA: 128(M) x 128(N). 8 warps 4m x 2n; warp 32x64.  (unchanged from R5)
// ============================================================================
__global__ __launch_bounds__(256, 2)
void gemm_down(const float* __restrict__ down_scale, float* __restrict__ out) {
    extern __shared__ __align__(128) char smem[];
    const uint32_t s0 = smem_u32(smem);
    const int tid = threadIdx.x;
    const int wid = tid >> 5, lane = tid & 31;
    const int rsel = lane & 15, csel = lane >> 4;
    const int wm = (wid & 3) * 32, wn = (wid >> 2) * 64;

    int mt, nt; tile_coords(blockIdx.x, NT_DN, mt, nt);
    const int m0 = mt * BM, n0 = nt * 128;

    const __half* pA = g_p16  + (size_t)m0 * Idim;
    const __half* pB = g_dw16 + (size_t)n0 * Idim;

    const int lr = tid >> 2, lc = tid & 3;
    const uint32_t offA1 = swzoff(lr, lc);
    const uint32_t offA2 = swzoff(lr + 64, lc);

    auto load_chunk = [&](int ch, int st) {
        uint32_t sb = s0 + st * STG_DN;
        size_t ga1 = (size_t)lr * Idim + ch * 32 + lc * 8;
        size_t ga2 = (size_t)(lr + 64) * Idim + ch * 32 + lc * 8;
        cpa16(sb + offA1,        pA + ga1);
        cpa16(sb + offA2,        pA + ga2);
        cpa16(sb + 8192 + offA1, pB + ga1);
        cpa16(sb + 8192 + offA2, pB + ga2);
        CP_COMMIT();
    };

    float cd[2][8][4];
    #pragma unroll
    for (int g = 0; g < 2; ++g)
        #pragma unroll
        for (int n = 0; n < 8; ++n)
            #pragma unroll
            for (int j = 0; j < 4; ++j) cd[g][n][j] = 0.f;

    #pragma unroll
    for (int p = 0; p < NST_DN - 1; ++p) load_chunk(p, p);

    for (int ch = 0; ch < NCH_DN; ++ch) {
        CP_WAIT(NST_DN - 2);
        __syncthreads();
        int nx = ch + NST_DN - 1;
        if (nx < NCH_DN) load_chunk(nx, nx % NST_DN);
        const uint32_t sb = s0 + (ch % NST_DN) * STG_DN;
        #pragma unroll
        for (int s = 0; s < 2; ++s) {
            uint32_t ah[2][4], bb[4][4];
            #pragma unroll
            for (int g = 0; g < 2; ++g)
                LDSM4(ah[g], swz(sb, wm + g * 16 + rsel, 2 * s + csel));
            #pragma unroll
            for (int bt = 0; bt < 4; ++bt)
                LDSM4(bb[bt], swz(sb + 8192, wn + bt * 16 + rsel, 2 * s + csel));
            #pragma unroll
            for (int g = 0; g < 2; ++g)
                #pragma unroll
                for (int n = 0; n < 8; ++n) {
                    int bt = n >> 1, sub = n & 1;
                    MMAF16(cd[g][n], ah[g], bb[bt][sub], bb[bt][2 + sub]);
                }
        }
    }

    #pragma unroll
    for (int n = 0; n < 8; ++n) {
        const int cn = n0 + wn + n * 8 + (lane & 3) * 2;
        const float ds0 = down_scale[cn], ds1 = down_scale[cn + 1];
        #pragma unroll
        for (int g = 0; g < 2; ++g) {
            const int rr = m0 + wm + g * 16 + (lane >> 2);
            float2 v0 = make_float2(cd[g][n][0] * ds0, cd[g][n][1] * ds1);
            float2 v1 = make_float2(cd[g][n][2] * ds0, cd[g][n][3] * ds1);
            *reinterpret_cast<float2*>(&out[(size_t)rr * Hdim + cn]) = v0;
            *reinterpret_cast<float2*>(&out[(size_t)(rr + 8) * Hdim + cn]) = v1;
        }
    }
}

// ============================================================================
// Launch
// ============================================================================
extern "C" void kernel_launch(void* const* d_in, const int* in_sizes, int n_in,
                              void* d_out, int out_size) {
    (void)in_sizes; (void)n_in; (void)out_size;
    const float* x          = (const float*)d_in[0];
    const int*   gate_wq    = (const int*)  d_in[1];
    const float* gate_scale = (const float*)d_in[2];
    const int*   up_wq      = (const int*)  d_in[3];
    const float* up_scale   = (const float*)d_in[4];
    const int*   down_wq    = (const int*)  d_in[5];
    const float* down_scale = (const float*)d_in[6];
    float* out = (float*)d_out;

    cudaFuncSetAttribute(gemm_gateup, cudaFuncAttributeMaxDynamicSharedMemorySize, SMEM_GU);
    cudaFuncSetAttribute(gemm_down,   cudaFuncAttributeMaxDynamicSharedMemorySize, SMEM_DN);

    size_t n4 = (size_t)Idim * Hdim / 4;
    pack_weights<<<(unsigned)((n4 + 255) / 256), 256>>>(gate_wq, up_wq, down_wq);
    size_t nx4 = (size_t)Mtot * Hdim / 4;
    cvt_x<<<(unsigned)((nx4 + 255) / 256), 256>>>(x);

    gemm_gateup<<<MT * NT_GU, 256, SMEM_GU>>>(gate_scale, up_scale);
    gemm_down<<<MT * NT_DN, 256, SMEM_DN>>>(down_scale, out);
}

// round 7
// speedup vs baseline: 3.8457x; 1.1066x over previous
#include <cuda_runtime.h>
#include <cuda_fp16.h>
#include <cstdint>

// ============================================================================
// Problem dims
// ============================================================================
static constexpr int Mtot = 8192;
static constexpr int Hdim = 4096;
static constexpr int Idim = 11008;

static constexpr int BM = 128;
static constexpr int MT = Mtot / BM;          // 64
static constexpr int BK = 64;                 // halves per k-chunk (128B rows)

// gate/up: BN=64 per output
static constexpr int NT_GU  = Idim / 64;      // 172
static constexpr int NCH_GU = Hdim / BK;      // 64
static constexpr int STG_GU = 32768;          // A 16K, Bg 8K, Bu 8K
static constexpr int NST    = 3;
static constexpr int SMEM_GU = NST * STG_GU;  // 98304

// down: BN=128
static constexpr int NT_DN  = Hdim / 128;     // 32
static constexpr int NCH_DN = Idim / BK;      // 172
static constexpr int STG_DN = 32768;          // A 16K, B 16K
static constexpr int SMEM_DN = NST * STG_DN;  // 98304

// ============================================================================
// Device scratch
// ============================================================================
__device__ __half g_gw16[(size_t)Idim * Hdim];
__device__ __half g_uw16[(size_t)Idim * Hdim];
__device__ __half g_dw16[(size_t)Hdim * Idim];
__device__ __half g_x16 [(size_t)Mtot * Hdim];
__device__ __half g_p16 [(size_t)Mtot * Idim];

// ============================================================================
// Primitives (sm_80-era PTX; compute_103-safe)
// ============================================================================
__device__ __forceinline__ uint32_t smem_u32(const void* p) {
    uint32_t a;
    asm("{ .reg .u64 t; cvta.to.shared.u64 t, %1; cvt.u32.u64 %0, t; }" : "=r"(a) : "l"(p));
    return a;
}
__device__ __forceinline__ void cpa16(uint32_t s, const void* g) {
    asm volatile("cp.async.cg.shared.global [%0], [%1], 16;" :: "r"(s), "l"(g));
}
#define CP_COMMIT() asm volatile("cp.async.commit_group;" ::: "memory")
#define CP_WAIT(N)  asm volatile("cp.async.wait_group %0;" :: "n"(N) : "memory")

#define LDSM4(r, addr) \
    asm volatile("ldmatrix.sync.aligned.m8n8.x4.shared.b16 {%0,%1,%2,%3}, [%4];" \
        : "=r"((r)[0]), "=r"((r)[1]), "=r"((r)[2]), "=r"((r)[3]) : "r"(addr))

#define MMAF16(d, a, b0, b1) \
    asm volatile("mma.sync.aligned.m16n8k16.row.col.f32.f16.f16.f32 " \
        "{%0,%1,%2,%3}, {%4,%5,%6,%7}, {%8,%9}, {%0,%1,%2,%3};" \
        : "+f"((d)[0]), "+f"((d)[1]), "+f"((d)[2]), "+f"((d)[3]) \
        : "r"((a)[0]), "r"((a)[1]), "r"((a)[2]), "r"((a)[3]), "r"(b0), "r"(b1))

// 128B rows, 8x16B chunks, swizzle c ^= (r&7): conflict-free for both the
// cp.async stores (fixed chunk, 8 consecutive rows -> 8 distinct chunks) and
// ldmatrix reads (fixed chunk, 8-row groups -> 8 distinct chunks).
__device__ __forceinline__ uint32_t swz(uint32_t base, int r, int c) {
    return base + r * 128 + (((c ^ (r & 7)) & 7) << 4);
}
__device__ __forceinline__ uint32_t swzoff(int r, int c) {
    return (uint32_t)(r * 128 + (((c ^ (r & 7)) & 7) << 4));
}

__device__ __forceinline__ void tile_coords(int bid, int nt, int& mt, int& ntile) {
    const int GROUP_M = 8;
    int per_group = GROUP_M * nt;
    int g = bid / per_group;
    int r = bid % per_group;
    int base = g * GROUP_M;
    int gm = MT - base; if (gm > GROUP_M) gm = GROUP_M;
    mt = base + (r % gm);
    ntile = r / gm;
}

// ============================================================================
// Prep: weights -> fp16 (exact, |w|<=127); x -> fp16 (RN)
// ============================================================================
__global__ void pack_weights(const int* __restrict__ gq, const int* __restrict__ uq,
                             const int* __restrict__ dq) {
    size_t i = (size_t)blockIdx.x * blockDim.x + threadIdx.x;
    size_t n4 = (size_t)Idim * Hdim / 4;
    if (i >= n4) return;
    int4 a = reinterpret_cast<const int4*>(gq)[i];
    int4 b = reinterpret_cast<const int4*>(uq)[i];
    int4 c = reinterpret_cast<const int4*>(dq)[i];
    __half2 a0 = __floats2half2_rn((float)a.x, (float)a.y);
    __half2 a1 = __floats2half2_rn((float)a.z, (float)a.w);
    __half2 b0 = __floats2half2_rn((float)b.x, (float)b.y);
    __half2 b1 = __floats2half2_rn((float)b.z, (float)b.w);
    __half2 c0 = __floats2half2_rn((float)c.x, (float)c.y);
    __half2 c1 = __floats2half2_rn((float)c.z, (float)c.w);
    reinterpret_cast<uint2*>(g_gw16)[i] =
        make_uint2(*reinterpret_cast<uint32_t*>(&a0), *reinterpret_cast<uint32_t*>(&a1));
    reinterpret_cast<uint2*>(g_uw16)[i] =
        make_uint2(*reinterpret_cast<uint32_t*>(&b0), *reinterpret_cast<uint32_t*>(&b1));
    reinterpret_cast<uint2*>(g_dw16)[i] =
        make_uint2(*reinterpret_cast<uint32_t*>(&c0), *reinterpret_cast<uint32_t*>(&c1));
}

__global__ void cvt_x(const float* __restrict__ x) {
    size_t i = (size_t)blockIdx.x * blockDim.x + threadIdx.x;
    size_t n4 = (size_t)Mtot * Hdim / 4;
    if (i >= n4) return;
    float4 v = reinterpret_cast<const float4*>(x)[i];
    __half2 h0 = __floats2half2_rn(v.x, v.y);
    __half2 h1 = __floats2half2_rn(v.z, v.w);
    reinterpret_cast<uint2*>(g_x16)[i] =
        make_uint2(*reinterpret_cast<uint32_t*>(&h0), *reinterpret_cast<uint32_t*>(&h1));
}

// ============================================================================
// Kernel A: fused gate+up fp16 GEMM -> p = (g*gs)*(u*us) in fp16
// CTA: 128(M) x 64(N per output). 8 warps 4m x 2n; warp 32x32 per output.
// BK=64, 3-stage cp.async, 4 k16-steps per barrier.
// ============================================================================
__global__ __launch_bounds__(256, 2)
void gemm_gateup(const float* __restrict__ gate_scale, const float* __restrict__ up_scale) {
    extern __shared__ __align__(128) char smem[];
    const uint32_t s0 = smem_u32(smem);
    const int tid = threadIdx.x;
    const int wid = tid >> 5, lane = tid & 31;
    const int rsel = lane & 15, csel = lane >> 4;
    const int wm = (wid & 3) * 32, wn = (wid >> 2) * 32;

    int mt, nt; tile_coords(blockIdx.x, NT_GU, mt, nt);
    const int m0 = mt * BM, n0 = nt * 64;

    const __half* pA  = g_x16  + (size_t)m0 * Hdim;
    const __half* pBg = g_gw16 + (size_t)n0 * Hdim;
    const __half* pBu = g_uw16 + (size_t)n0 * Hdim;

    // loader: lr = row (0..31), lc = 16B chunk (0..7)
    const int lr = tid >> 3, lc = tid & 7;
    uint32_t offA[4], offB[2];
    #pragma unroll
    for (int j = 0; j < 4; ++j) offA[j] = swzoff(lr + 32 * j, lc);
    #pragma unroll
    for (int j = 0; j < 2; ++j) offB[j] = swzoff(lr + 32 * j, lc);

    auto load_chunk = [&](int ch, int st) {
        uint32_t sb = s0 + st * STG_GU;
        size_t gk = (size_t)ch * BK + lc * 8;
        #pragma unroll
        for (int j = 0; j < 4; ++j)
            cpa16(sb + offA[j], pA + (size_t)(lr + 32 * j) * Hdim + gk);
        #pragma unroll
        for (int j = 0; j < 2; ++j) {
            cpa16(sb + 16384 + offB[j], pBg + (size_t)(lr + 32 * j) * Hdim + gk);
            cpa16(sb + 24576 + offB[j], pBu + (size_t)(lr + 32 * j) * Hdim + gk);
        }
        CP_COMMIT();
    };

    float cg[2][4][4], cu[2][4][4];
    #pragma unroll
    for (int g = 0; g < 2; ++g)
        #pragma unroll
        for (int n = 0; n < 4; ++n)
            #pragma unroll
            for (int j = 0; j < 4; ++j) { cg[g][n][j] = 0.f; cu[g][n][j] = 0.f; }

    load_chunk(0, 0);
    load_chunk(1, 1);

    for (int ch = 0; ch < NCH_GU; ++ch) {
        CP_WAIT(1);
        __syncthreads();
        int nx = ch + 2;
        if (nx < NCH_GU) load_chunk(nx, nx % NST);
        const uint32_t sb = s0 + (ch % NST) * STG_GU;
        #pragma unroll
        for (int s = 0; s < 4; ++s) {
            const int cc = 2 * s + csel;
            uint32_t ah[2][4], bg[2][4], bu[2][4];
            #pragma unroll
            for (int g = 0; g < 2; ++g)
                LDSM4(ah[g], swz(sb, wm + g * 16 + rsel, cc));
            #pragma unroll
            for (int bt = 0; bt < 2; ++bt) {
                LDSM4(bg[bt], swz(sb + 16384, wn + bt * 16 + rsel, cc));
                LDSM4(bu[bt], swz(sb + 24576, wn + bt * 16 + rsel, cc));
            }
            #pragma unroll
            for (int g = 0; g < 2; ++g)
                #pragma unroll
                for (int n = 0; n < 4; ++n) {
                    int bt = n >> 1, sub = n & 1;
                    MMAF16(cg[g][n], ah[g], bg[bt][sub], bg[bt][2 + sub]);
                    MMAF16(cu[g][n], ah[g], bu[bt][sub], bu[bt][2 + sub]);
                }
        }
    }

    // Epilogue: p = (g*gs)*(u*us) -> half2
    #pragma unroll
    for (int n = 0; n < 4; ++n) {
        const int cn = n0 + wn + n * 8 + (lane & 3) * 2;
        const float gs0 = gate_scale[cn], gs1 = gate_scale[cn + 1];
        const float us0 = up_scale[cn],   us1 = up_scale[cn + 1];
        #pragma unroll
        for (int g = 0; g < 2; ++g) {
            const int rr = m0 + wm + g * 16 + (lane >> 2);
            float p00 = (cg[g][n][0] * gs0) * (cu[g][n][0] * us0);
            float p01 = (cg[g][n][1] * gs1) * (cu[g][n][1] * us1);
            float p10 = (cg[g][n][2] * gs0) * (cu[g][n][2] * us0);
            float p11 = (cg[g][n][3] * gs1) * (cu[g][n][3] * us1);
            __half2 q0 = __floats2half2_rn(p00, p01);
            __half2 q1 = __floats2half2_rn(p10, p11);
            *reinterpret_cast<__half2*>(&g_p16[(size_t)rr * Idim + cn]) = q0;
            *reinterpret_cast<__half2*>(&g_p16[(size_t)(rr + 8) * Idim + cn]) = q1;
        }
    }
}

// ============================================================================
// Kernel B: down GEMM.  out = down_scale * (p @ dw^T)
// CTA: 128(M) x 128(N). 8 warps 4m x 2n; warp 32x64. BK=64, 3-stage.
// ============================================================================
__global__ __launch_bounds__(256, 2)
void gemm_down(const float* __restrict__ down_scale, float* __restrict__ out) {
    extern __shared__ __align__(128) char smem[];
    const uint32_t s0 = smem_u32(smem);
    const int tid = threadIdx.x;
    const int wid = tid >> 5, lane = tid & 31;
    const int rsel = lane & 15, csel = lane >> 4;
    const int wm = (wid & 3) * 32, wn = (wid >> 2) * 64;

    int mt, nt; tile_coords(blockIdx.x, NT_DN, mt, nt);
    const int m0 = mt * BM, n0 = nt * 128;

    const __half* pA = g_p16  + (size_t)m0 * Idim;
    const __half* pB = g_dw16 + (size_t)n0 * Idim;

    const int lr = tid >> 3, lc = tid & 7;
    uint32_t offR[4];
    #pragma unroll
    for (int j = 0; j < 4; ++j) offR[j] = swzoff(lr + 32 * j, lc);

    auto load_chunk = [&](int ch, int st) {
        uint32_t sb = s0 + st * STG_DN;
        size_t gk = (size_t)ch * BK + lc * 8;
        #pragma unroll
        for (int j = 0; j < 4; ++j) {
            cpa16(sb + offR[j],         pA + (size_t)(lr + 32 * j) * Idim + gk);
            cpa16(sb + 16384 + offR[j], pB + (size_t)(lr + 32 * j) * Idim + gk);
        }
        CP_COMMIT();
    };

    float cd[2][8][4];
    #pragma unroll
    for (int g = 0; g < 2; ++g)
        #pragma unroll
        for (int n = 0; n < 8; ++n)
            #pragma unroll
            for (int j = 0; j < 4; ++j) cd[g][n][j] = 0.f;

    load_chunk(0, 0);
    load_chunk(1, 1);

    for (int ch = 0; ch < NCH_DN; ++ch) {
        CP_WAIT(1);
        __syncthreads();
        int nx = ch + 2;
        if (nx < NCH_DN) load_chunk(nx, nx % NST);
        const uint32_t sb = s0 + (ch % NST) * STG_DN;
        #pragma unroll
        for (int s = 0; s < 4; ++s) {
            const int cc = 2 * s + csel;
            uint32_t ah[2][4], bb[4][4];
            #pragma unroll
            for (int g = 0; g < 2; ++g)
                LDSM4(ah[g], swz(sb, wm + g * 16 + rsel, cc));
            #pragma unroll
            for (int bt = 0; bt < 4; ++bt)
                LDSM4(bb[bt], swz(sb + 16384, wn + bt * 16 + rsel, cc));
            #pragma unroll
            for (int g = 0; g < 2; ++g)
                #pragma unroll
                for (int n = 0; n < 8; ++n) {
                    int bt = n >> 1, sub = n & 1;
                    MMAF16(cd[g][n], ah[g], bb[bt][sub], bb[bt][2 + sub]);
                }
        }
    }

    #pragma unroll
    for (int n = 0; n < 8; ++n) {
        const int cn = n0 + wn + n * 8 + (lane & 3) * 2;
        const float ds0 = down_scale[cn], ds1 = down_scale[cn + 1];
        #pragma unroll
        for (int g = 0; g < 2; ++g) {
            const int rr = m0 + wm + g * 16 + (lane >> 2);
            float2 v0 = make_float2(cd[g][n][0] * ds0, cd[g][n][1] * ds1);
            float2 v1 = make_float2(cd[g][n][2] * ds0, cd[g][n][3] * ds1);
            *reinterpret_cast<float2*>(&out[(size_t)rr * Hdim + cn]) = v0;
            *reinterpret_cast<float2*>(&out[(size_t)(rr + 8) * Hdim + cn]) = v1;
        }
    }
}

// ============================================================================
// Launch
// ============================================================================
extern "C" void kernel_launch(void* const* d_in, const int* in_sizes, int n_in,
                              void* d_out, int out_size) {
    (void)in_sizes; (void)n_in; (void)out_size;
    const float* x          = (const float*)d_in[0];
    const int*   gate_wq    = (const int*)  d_in[1];
    const float* gate_scale = (const float*)d_in[2];
    const int*   up_wq      = (const int*)  d_in[3];
    const float* up_scale   = (const float*)d_in[4];
    const int*   down_wq    = (const int*)  d_in[5];
    const float* down_scale = (const float*)d_in[6];
    float* out = (float*)d_out;

    cudaFuncSetAttribute(gemm_gateup, cudaFuncAttributeMaxDynamicSharedMemorySize, SMEM_GU);
    cudaFuncSetAttribute(gemm_down,   cudaFuncAttributeMaxDynamicSharedMemorySize, SMEM_DN);

    size_t n4 = (size_t)Idim * Hdim / 4;
    pack_weights<<<(unsigned)((n4 + 255) / 256), 256>>>(gate_wq, up_wq, down_wq);
    size_t nx4 = (size_t)Mtot * Hdim / 4;
    cvt_x<<<(unsigned)((nx4 + 255) / 256), 256>>>(x);

    gemm_gateup<<<MT * NT_GU, 256, SMEM_GU>>>(gate_scale, up_scale);
    gemm_down<<<MT * NT_DN, 256, SMEM_DN>>>(down_scale, out);
}